// round 1
// baseline (speedup 1.0000x reference)
#include <cuda_runtime.h>
#include <cuda_bf16.h>

// RNN1: B=16384, T=256, I=5, H=2, F=128, C=1
// x:[B,T,I] f32 ; W_ih:[2,5] ; W_hh:[2,2] ; b_ih,b_hh:[2] ; W1:[128,2] ; b1:[128] ; W2:[1,128] ; b2:[1]
// out:[B,1] f32

#define T_STEPS 256
#define NGROUPS (T_STEPS / 4)   // 64 groups of 4 timesteps (20 floats = 5 x float4)
#define PF 4                    // prefetch distance in groups

__device__ __forceinline__ float ex2_approx(float x) {
    float y; asm("ex2.approx.f32 %0, %1;" : "=f"(y) : "f"(x)); return y;
}
__device__ __forceinline__ float rcp_approx(float x) {
    float y; asm("rcp.approx.f32 %0, %1;" : "=f"(y) : "f"(x)); return y;
}
// z = 2*log2(e)*arg  ->  tanh(arg) = 1 - 2/(2^z + 1)
__device__ __forceinline__ float tanh_scaled(float z) {
    float e = ex2_approx(z);
    float r = rcp_approx(e + 1.0f);
    return fmaf(-2.0f, r, 1.0f);
}

__global__ void __launch_bounds__(32, 8) rnn1_kernel(
    const float* __restrict__ x,
    const float* __restrict__ Wih, const float* __restrict__ Whh,
    const float* __restrict__ bih, const float* __restrict__ bhh,
    const float* __restrict__ W1,  const float* __restrict__ b1,
    const float* __restrict__ W2,  const float* __restrict__ b2,
    float* __restrict__ out)
{
    const int b = blockIdx.x * 32 + threadIdx.x;

    // Fold 2*log2(e) into all recurrence weights/biases so the tanh argument
    // arrives pre-scaled for ex2.
    const float S = 2.885390081777926815f;  // 2 / ln(2)
    float wi0[5], wi1[5];
#pragma unroll
    for (int i = 0; i < 5; ++i) { wi0[i] = S * Wih[i]; wi1[i] = S * Wih[5 + i]; }
    const float a00 = S * Whh[0], a01 = S * Whh[1];
    const float a10 = S * Whh[2], a11 = S * Whh[3];
    const float c0 = S * (bih[0] + bhh[0]);
    const float c1 = S * (bih[1] + bhh[1]);

    const float4* __restrict__ row =
        reinterpret_cast<const float4*>(x + (size_t)b * (T_STEPS * 5));

    // Prime the software pipeline: PF groups in flight.
    float4 buf[PF][5];
#pragma unroll
    for (int p = 0; p < PF; ++p)
#pragma unroll
        for (int j = 0; j < 5; ++j) buf[p][j] = row[5 * p + j];

    float h0 = 0.0f, h1 = 0.0f;

    // One recurrence step from 5 raw x values.
#define RNN_STEP(x0, x1, x2, x3, x4)                                   \
    do {                                                               \
        float p0 = c0, p1 = c1;                                        \
        p0 = fmaf(wi0[0], (x0), p0);  p1 = fmaf(wi1[0], (x0), p1);     \
        p0 = fmaf(wi0[1], (x1), p0);  p1 = fmaf(wi1[1], (x1), p1);     \
        p0 = fmaf(wi0[2], (x2), p0);  p1 = fmaf(wi1[2], (x2), p1);     \
        p0 = fmaf(wi0[3], (x3), p0);  p1 = fmaf(wi1[3], (x3), p1);     \
        p0 = fmaf(wi0[4], (x4), p0);  p1 = fmaf(wi1[4], (x4), p1);     \
        float z0 = fmaf(a01, h1, fmaf(a00, h0, p0));                   \
        float z1 = fmaf(a11, h1, fmaf(a10, h0, p1));                   \
        h0 = tanh_scaled(z0);                                          \
        h1 = tanh_scaled(z1);                                          \
    } while (0)

#pragma unroll 4   // multiple of PF so buf indices are compile-time constant
    for (int g = 0; g < NGROUPS; ++g) {
        const int s = g & (PF - 1);
        float4 q0 = buf[s][0], q1 = buf[s][1], q2 = buf[s][2],
               q3 = buf[s][3], q4 = buf[s][4];
        if (g + PF < NGROUPS) {
#pragma unroll
            for (int j = 0; j < 5; ++j) buf[s][j] = row[5 * (g + PF) + j];
        }
        RNN_STEP(q0.x, q0.y, q0.z, q0.w, q1.x);
        RNN_STEP(q1.y, q1.z, q1.w, q2.x, q2.y);
        RNN_STEP(q2.z, q2.w, q3.x, q3.y, q3.z);
        RNN_STEP(q3.w, q4.x, q4.y, q4.z, q4.w);
    }
#undef RNN_STEP

    // Head: relu(h) -> FC(2->128) + relu -> FC(128->1)
    const float r0 = fmaxf(h0, 0.0f);
    const float r1 = fmaxf(h1, 0.0f);
    const float2* __restrict__ W1v = reinterpret_cast<const float2*>(W1);
    float acc = b2[0];
#pragma unroll 8
    for (int f = 0; f < 128; ++f) {
        float2 w = W1v[f];
        float t = fmaf(w.x, r0, fmaf(w.y, r1, b1[f]));
        acc = fmaf(fmaxf(t, 0.0f), W2[f], acc);
    }
    out[b] = acc;
}

extern "C" void kernel_launch(void* const* d_in, const int* in_sizes, int n_in,
                              void* d_out, int out_size)
{
    const float* x   = (const float*)d_in[0];
    const float* Wih = (const float*)d_in[1];
    const float* Whh = (const float*)d_in[2];
    const float* bih = (const float*)d_in[3];
    const float* bhh = (const float*)d_in[4];
    const float* W1  = (const float*)d_in[5];
    const float* b1  = (const float*)d_in[6];
    const float* W2  = (const float*)d_in[7];
    const float* b2  = (const float*)d_in[8];
    float* out = (float*)d_out;

    // 16384 rows, 1 thread per row, 32-thread blocks -> 512 blocks spread
    // evenly across all SMs.
    rnn1_kernel<<<512, 32>>>(x, Wih, Whh, bih, bhh, W1, b1, W2, b2, out);
}

// round 3
// speedup vs baseline: 1.0138x; 1.0138x over previous
#include <cuda_runtime.h>
#include <cuda_bf16.h>
#include <cstdint>

// RNN1: B=16384, T=256, I=5, H=2, F=128, C=1
// One warp per block; each block owns 32 batch rows (lane = row).
// x is staged gmem->smem with cp.async in time-chunks of 32 steps so that
// every LDGSTS touches exactly 4 aligned 128B lines (perfect coalescing).

#define T_STEPS   256
#define C_STEPS   32                    // timesteps per chunk
#define NCHUNK    (T_STEPS / C_STEPS)   // 8
#define F4_CHUNK  40                    // float4 per row per chunk (32*5 floats)
#define ROWPAD    41                    // padded row stride in float4 (bank spread)
#define ROWS      32                    // batch rows per block

__device__ __forceinline__ float ex2_approx(float x) {
    float y; asm("ex2.approx.f32 %0, %1;" : "=f"(y) : "f"(x)); return y;
}
__device__ __forceinline__ float rcp_approx(float x) {
    float y; asm("rcp.approx.f32 %0, %1;" : "=f"(y) : "f"(x)); return y;
}
// z = 2*log2(e)*arg  ->  tanh(arg) = 1 - 2/(2^z + 1)
__device__ __forceinline__ float tanh_scaled(float z) {
    float e = ex2_approx(z);
    float r = rcp_approx(e + 1.0f);
    return fmaf(-2.0f, r, 1.0f);
}

__device__ __forceinline__ void cp_async16(unsigned int dst_smem, const void* src) {
    asm volatile("cp.async.cg.shared.global [%0], [%1], 16;\n"
                 :: "r"(dst_smem), "l"(src));
}

__global__ void __launch_bounds__(32) rnn1_kernel(
    const float* __restrict__ x,
    const float* __restrict__ Wih, const float* __restrict__ Whh,
    const float* __restrict__ bih, const float* __restrict__ bhh,
    const float* __restrict__ W1,  const float* __restrict__ b1,
    const float* __restrict__ W2,  const float* __restrict__ b2,
    float* __restrict__ out)
{
    __shared__ float4 tile[2][ROWS * ROWPAD];   // 2 x 20.5 KB = 41 KB

    const int lane = threadIdx.x;
    const int row0 = blockIdx.x * ROWS;

    // ---- fold 2*log2(e) into recurrence weights/biases ----
    const float S = 2.885390081777926815f;  // 2 / ln(2)
    float wi0[5], wi1[5];
#pragma unroll
    for (int i = 0; i < 5; ++i) { wi0[i] = S * Wih[i]; wi1[i] = S * Wih[5 + i]; }
    const float a00 = S * Whh[0], a01 = S * Whh[1];
    const float a10 = S * Whh[2], a11 = S * Whh[3];
    const float c0 = S * (bih[0] + bhh[0]);
    const float c1 = S * (bih[1] + bhh[1]);

    // x as float4: 320 float4 per row; chunk c covers [c*40, c*40+40)
    const float4* __restrict__ xf4 =
        reinterpret_cast<const float4*>(x) + (size_t)row0 * 320;

    const unsigned int smem_base =
        (unsigned int)__cvta_generic_to_shared(&tile[0][0]);

    // ---- coalesced chunk loader: 40 LDGSTS, each hitting 4 aligned lines ----
    auto issue_chunk = [&](int chunk, int buf) {
#pragma unroll
        for (int i = 0; i < F4_CHUNK; ++i) {
            const int li  = i * 32 + lane;          // 0..1279
            const int r   = li / F4_CHUNK;          // row within block
            const int off = li % F4_CHUNK;          // float4 within row-chunk
            const float4* src = xf4 + (size_t)r * 320 + chunk * F4_CHUNK + off;
            const unsigned int dst = smem_base +
                ((unsigned int)(buf * (ROWS * ROWPAD)) + r * ROWPAD + off) * 16u;
            cp_async16(dst, src);
        }
        asm volatile("cp.async.commit_group;");
    };

    float h0 = 0.0f, h1 = 0.0f;

#define RNN_STEP(x0, x1, x2, x3, x4)                                   \
    do {                                                               \
        float p0 = c0, p1 = c1;                                        \
        p0 = fmaf(wi0[0], (x0), p0);  p1 = fmaf(wi1[0], (x0), p1);     \
        p0 = fmaf(wi0[1], (x1), p0);  p1 = fmaf(wi1[1], (x1), p1);     \
        p0 = fmaf(wi0[2], (x2), p0);  p1 = fmaf(wi1[2], (x2), p1);     \
        p0 = fmaf(wi0[3], (x3), p0);  p1 = fmaf(wi1[3], (x3), p1);     \
        p0 = fmaf(wi0[4], (x4), p0);  p1 = fmaf(wi1[4], (x4), p1);     \
        float z0 = fmaf(a01, h1, fmaf(a00, h0, p0));                   \
        float z1 = fmaf(a11, h1, fmaf(a10, h0, p1));                   \
        h0 = tanh_scaled(z0);                                          \
        h1 = tanh_scaled(z1);                                          \
    } while (0)

    // compute 32 timesteps out of tile[buf], lane = row
    auto compute_chunk = [&](int buf) {
        const float4* __restrict__ myrow = &tile[buf][lane * ROWPAD];
#pragma unroll
        for (int j = 0; j < 8; ++j) {               // 8 groups of 4 steps
            float4 q0 = myrow[5 * j + 0];
            float4 q1 = myrow[5 * j + 1];
            float4 q2 = myrow[5 * j + 2];
            float4 q3 = myrow[5 * j + 3];
            float4 q4 = myrow[5 * j + 4];
            RNN_STEP(q0.x, q0.y, q0.z, q0.w, q1.x);
            RNN_STEP(q1.y, q1.z, q1.w, q2.x, q2.y);
            RNN_STEP(q2.z, q2.w, q3.x, q3.y, q3.z);
            RNN_STEP(q3.w, q4.x, q4.y, q4.z, q4.w);
        }
    };

    // ---- software pipeline: double buffer, depth 1 chunk ----
    issue_chunk(0, 0);
    issue_chunk(1, 1);

    for (int g = 0; g < NCHUNK - 1; ++g) {          // g = 0..6
        asm volatile("cp.async.wait_group 1;");     // chunk g resident
        __syncwarp();
        compute_chunk(g & 1);
        if (g + 2 < NCHUNK)                         // refill freed buffer
            issue_chunk(g + 2, g & 1);
    }
    asm volatile("cp.async.wait_group 0;");         // final chunk resident
    __syncwarp();
    compute_chunk((NCHUNK - 1) & 1);
#undef RNN_STEP

    // ---- head: relu(h) -> FC(2->128) + relu -> FC(128->1) ----
    const float r0 = fmaxf(h0, 0.0f);
    const float r1 = fmaxf(h1, 0.0f);
    const float2* __restrict__ W1v = reinterpret_cast<const float2*>(W1);
    float acc = b2[0];
#pragma unroll 8
    for (int f = 0; f < 128; ++f) {
        float2 w = W1v[f];
        float t = fmaf(w.x, r0, fmaf(w.y, r1, b1[f]));
        acc = fmaf(fmaxf(t, 0.0f), W2[f], acc);
    }
    out[row0 + lane] = acc;
}

extern "C" void kernel_launch(void* const* d_in, const int* in_sizes, int n_in,
                              void* d_out, int out_size)
{
    const float* x   = (const float*)d_in[0];
    const float* Wih = (const float*)d_in[1];
    const float* Whh = (const float*)d_in[2];
    const float* bih = (const float*)d_in[3];
    const float* bhh = (const float*)d_in[4];
    const float* W1  = (const float*)d_in[5];
    const float* b1  = (const float*)d_in[6];
    const float* W2  = (const float*)d_in[7];
    const float* b2  = (const float*)d_in[8];
    float* out = (float*)d_out;

    rnn1_kernel<<<512, 32>>>(x, Wih, Whh, bih, bhh, W1, b1, W2, b2, out);
}

// round 4
// speedup vs baseline: 1.1389x; 1.1233x over previous
#include <cuda_runtime.h>
#include <cuda_bf16.h>
#include <cstdint>

// RNN1: B=16384, T=256, I=5, H=2, F=128, C=1
// 128-thread blocks (4 warps -> all 4 SMSPs). Each warp owns 32 batch rows
// with an independent cp.async double-buffered pipeline in dynamic smem.
// Chunk = 32 timesteps = 40 float4 per row. Loader maps 8-lane groups to
// single 128B lines: every LDGSTS touches exactly 4 aligned lines and all
// addresses are base + compile-time immediates.

#define CH        32                    // timesteps per chunk
#define NCH       8                     // chunks (256/32)
#define F4C       40                    // float4 per row per chunk
#define RP        41                    // padded row stride in float4
#define WTILE     (32 * RP)             // 1312 float4 per warp-buffer
#define SMEM_BYTES (4 * 2 * WTILE * 16) // 167936

__device__ __forceinline__ float ex2_approx(float x) {
    float y; asm("ex2.approx.f32 %0, %1;" : "=f"(y) : "f"(x)); return y;
}
__device__ __forceinline__ float rcp_approx(float x) {
    float y; asm("rcp.approx.f32 %0, %1;" : "=f"(y) : "f"(x)); return y;
}
// z = 2*log2(e)*arg  ->  tanh(arg) = 1 - 2/(2^z + 1)
__device__ __forceinline__ float tanh_scaled(float z) {
    float e = ex2_approx(z);
    float r = rcp_approx(e + 1.0f);
    return fmaf(-2.0f, r, 1.0f);
}

__device__ __forceinline__ void cp_async16(unsigned int dst_smem, const void* src) {
    asm volatile("cp.async.cg.shared.global [%0], [%1], 16;\n"
                 :: "r"(dst_smem), "l"(src));
}

extern __shared__ float4 tile[];   // [4 warps][2 bufs][32 rows][41 f4]

__global__ void __launch_bounds__(128, 1) rnn1_kernel(
    const float* __restrict__ x,
    const float* __restrict__ Wih, const float* __restrict__ Whh,
    const float* __restrict__ bih, const float* __restrict__ bhh,
    const float* __restrict__ W1,  const float* __restrict__ b1,
    const float* __restrict__ W2,  const float* __restrict__ b2,
    float* __restrict__ out)
{
    const int lane = threadIdx.x & 31;
    const int wid  = threadIdx.x >> 5;
    const int warp_row0 = blockIdx.x * 128 + wid * 32;   // first row of this warp

    // ---- fold 2*log2(e) into recurrence weights/biases ----
    const float S = 2.885390081777926815f;  // 2 / ln(2)
    float wi0[5], wi1[5];
#pragma unroll
    for (int i = 0; i < 5; ++i) { wi0[i] = S * Wih[i]; wi1[i] = S * Wih[5 + i]; }
    const float a00 = S * Whh[0], a01 = S * Whh[1];
    const float a10 = S * Whh[2], a11 = S * Whh[3];
    const float c0 = S * (bih[0] + bhh[0]);
    const float c1 = S * (bih[1] + bhh[1]);

    // x as float4: 320 per row. Warp-local base.
    const float4* __restrict__ xw =
        reinterpret_cast<const float4*>(x) + (size_t)warp_row0 * 320;

    // ---- loader lane mapping: group g = lane/8 handles rows 4j+g,
    //      sub = lane%8 covers one 128B line (8 f4) per (j,k) step. ----
    const int grp = lane >> 3;
    const int sub = lane & 7;

    // per-lane gmem base (chunk 0): row=grp (j=0), f4 = sub (k=0)
    const float4* src_base = xw + grp * 320 + sub;

    const unsigned int smem0 = (unsigned int)__cvta_generic_to_shared(tile);
    // per-lane smem dst base for buf 0 / buf 1 (bytes)
    const unsigned int dst0 =
        smem0 + (unsigned int)((wid * 2 * WTILE) + grp * RP + sub) * 16u;
    const unsigned int dst1 = dst0 + (unsigned int)WTILE * 16u;

    // one chunk = 40 LDGSTS, each exactly 4 aligned 128B lines
    auto issue_chunk = [&](int chunk, int buf) {
        const float4* s = src_base + chunk * F4C;
        const unsigned int d = buf ? dst1 : dst0;
#pragma unroll
        for (int j = 0; j < 8; ++j)         // row quads: rows 4j+grp
#pragma unroll
            for (int k = 0; k < 5; ++k)     // 5 lines per row-chunk
                cp_async16(d + (unsigned int)(j * 4 * RP + k * 8) * 16u,
                           s + j * 4 * 320 + k * 8);
        asm volatile("cp.async.commit_group;");
    };

    float h0 = 0.0f, h1 = 0.0f;

#define RNN_STEP(x0, x1, x2, x3, x4)                                   \
    do {                                                               \
        float p0 = c0, p1 = c1;                                        \
        p0 = fmaf(wi0[0], (x0), p0);  p1 = fmaf(wi1[0], (x0), p1);     \
        p0 = fmaf(wi0[1], (x1), p0);  p1 = fmaf(wi1[1], (x1), p1);     \
        p0 = fmaf(wi0[2], (x2), p0);  p1 = fmaf(wi1[2], (x2), p1);     \
        p0 = fmaf(wi0[3], (x3), p0);  p1 = fmaf(wi1[3], (x3), p1);     \
        p0 = fmaf(wi0[4], (x4), p0);  p1 = fmaf(wi1[4], (x4), p1);     \
        float z0 = fmaf(a01, h1, fmaf(a00, h0, p0));                   \
        float z1 = fmaf(a11, h1, fmaf(a10, h0, p1));                   \
        h0 = tanh_scaled(z0);                                          \
        h1 = tanh_scaled(z1);                                          \
    } while (0)

    // compute 32 timesteps out of buf; lane = row within warp
    const float4* myrow0 = &tile[wid * 2 * WTILE + lane * RP];
    auto compute_chunk = [&](int buf) {
        const float4* __restrict__ myrow = myrow0 + buf * WTILE;
#pragma unroll
        for (int j = 0; j < 8; ++j) {               // 8 groups of 4 steps
            float4 q0 = myrow[5 * j + 0];
            float4 q1 = myrow[5 * j + 1];
            float4 q2 = myrow[5 * j + 2];
            float4 q3 = myrow[5 * j + 3];
            float4 q4 = myrow[5 * j + 4];
            RNN_STEP(q0.x, q0.y, q0.z, q0.w, q1.x);
            RNN_STEP(q1.y, q1.z, q1.w, q2.x, q2.y);
            RNN_STEP(q2.z, q2.w, q3.x, q3.y, q3.z);
            RNN_STEP(q3.w, q4.x, q4.y, q4.z, q4.w);
        }
    };

    // ---- per-warp software pipeline: double buffer ----
    issue_chunk(0, 0);
    issue_chunk(1, 1);

    for (int g = 0; g < NCH - 1; ++g) {             // g = 0..6
        asm volatile("cp.async.wait_group 1;");     // chunk g resident (this thread)
        __syncwarp();                               // ... and all lanes' loads
        compute_chunk(g & 1);
        if (g + 2 < NCH)
            issue_chunk(g + 2, g & 1);
    }
    asm volatile("cp.async.wait_group 0;");
    __syncwarp();
    compute_chunk((NCH - 1) & 1);
#undef RNN_STEP

    // ---- head: relu(h) -> FC(2->128) + relu -> FC(128->1) ----
    const float r0 = fmaxf(h0, 0.0f);
    const float r1 = fmaxf(h1, 0.0f);
    const float2* __restrict__ W1v = reinterpret_cast<const float2*>(W1);
    float acc = b2[0];
#pragma unroll 8
    for (int f = 0; f < 128; ++f) {
        float2 w = W1v[f];
        float t = fmaf(w.x, r0, fmaf(w.y, r1, b1[f]));
        acc = fmaf(fmaxf(t, 0.0f), W2[f], acc);
    }
    out[warp_row0 + lane] = acc;
}

extern "C" void kernel_launch(void* const* d_in, const int* in_sizes, int n_in,
                              void* d_out, int out_size)
{
    const float* x   = (const float*)d_in[0];
    const float* Wih = (const float*)d_in[1];
    const float* Whh = (const float*)d_in[2];
    const float* bih = (const float*)d_in[3];
    const float* bhh = (const float*)d_in[4];
    const float* W1  = (const float*)d_in[5];
    const float* b1  = (const float*)d_in[6];
    const float* W2  = (const float*)d_in[7];
    const float* b2  = (const float*)d_in[8];
    float* out = (float*)d_out;

    static int smem_set = 0;
    if (!smem_set) {
        cudaFuncSetAttribute(rnn1_kernel,
                             cudaFuncAttributeMaxDynamicSharedMemorySize,
                             SMEM_BYTES);
        smem_set = 1;
    }

    // 16384 rows / 128 rows per block = 128 blocks of 128 threads.
    rnn1_kernel<<<128, 128, SMEM_BYTES>>>(x, Wih, Whh, bih, bhh,
                                          W1, b1, W2, b2, out);
}

// round 6
// speedup vs baseline: 1.1440x; 1.0045x over previous
#include <cuda_runtime.h>
#include <cuda_bf16.h>
#include <cstdint>

// RNN1: B=16384, T=256, I=5, H=2, F=128, C=1
// 128-thread blocks (4 warps -> all 4 SMSPs), 32 rows per warp, lane = row.
// cp.async double-buffered staging (32-step chunks, perfectly coalesced).
// Inner loop restructured: all x-projections for a 4-step group are computed
// up front (no h dependence) so only z-FMA + ex2/rcp sit on the serial chain.

#define NCH       8                     // chunks (256/32)
#define F4C       40                    // float4 per row per chunk
#define RP        41                    // padded row stride in float4
#define WTILE     (32 * RP)             // float4 per warp-buffer
#define SMEM_BYTES (4 * 2 * WTILE * 16) // 167936

__device__ __forceinline__ float ex2_approx(float x) {
    float y; asm("ex2.approx.f32 %0, %1;" : "=f"(y) : "f"(x)); return y;
}
__device__ __forceinline__ float rcp_approx(float x) {
    float y; asm("rcp.approx.f32 %0, %1;" : "=f"(y) : "f"(x)); return y;
}

__device__ __forceinline__ void cp_async16(unsigned int dst_smem, const void* src) {
    asm volatile("cp.async.cg.shared.global [%0], [%1], 16;\n"
                 :: "r"(dst_smem), "l"(src));
}

extern __shared__ float4 tile[];   // [4 warps][2 bufs][32 rows][41 f4]

__global__ void __launch_bounds__(128, 1) rnn1_kernel(
    const float* __restrict__ x,
    const float* __restrict__ Wih, const float* __restrict__ Whh,
    const float* __restrict__ bih, const float* __restrict__ bhh,
    const float* __restrict__ W1,  const float* __restrict__ b1,
    const float* __restrict__ W2,  const float* __restrict__ b2,
    float* __restrict__ out)
{
    const int lane = threadIdx.x & 31;
    const int wid  = threadIdx.x >> 5;
    const int warp_row0 = blockIdx.x * 128 + wid * 32;

    // ---- fold 2*log2(e) into recurrence weights/biases ----
    const float S = 2.885390081777926815f;  // 2 / ln(2)
    float wi0[5], wi1[5];
#pragma unroll
    for (int i = 0; i < 5; ++i) { wi0[i] = S * Wih[i]; wi1[i] = S * Wih[5 + i]; }
    const float a00 = S * Whh[0], a01 = S * Whh[1];
    const float a10 = S * Whh[2], a11 = S * Whh[3];
    const float c0 = S * (bih[0] + bhh[0]);
    const float c1 = S * (bih[1] + bhh[1]);

    const float4* __restrict__ xw =
        reinterpret_cast<const float4*>(x) + (size_t)warp_row0 * 320;

    // loader mapping: 8-lane group <-> one 128B line; grp handles rows 4j+grp
    const int grp = lane >> 3;
    const int sub = lane & 7;
    const float4* src_base = xw + grp * 320 + sub;

    const unsigned int smem0 = (unsigned int)__cvta_generic_to_shared(tile);
    const unsigned int dst0 =
        smem0 + (unsigned int)((wid * 2 * WTILE) + grp * RP + sub) * 16u;
    const unsigned int dst1 = dst0 + (unsigned int)WTILE * 16u;

    auto issue_chunk = [&](int chunk, int buf) {
        const float4* s = src_base + chunk * F4C;
        const unsigned int d = buf ? dst1 : dst0;
#pragma unroll
        for (int j = 0; j < 8; ++j)
#pragma unroll
            for (int k = 0; k < 5; ++k)
                cp_async16(d + (unsigned int)(j * 4 * RP + k * 8) * 16u,
                           s + j * 4 * 320 + k * 8);
        asm volatile("cp.async.commit_group;");
    };

    float h0 = 0.0f, h1 = 0.0f;

    // projection of one timestep's 5 inputs (no h dependence)
#define PROJ(pa, pb, x0, x1, x2, x3, x4)                               \
    do {                                                               \
        pa = fmaf(wi0[0], (x0), pa);  pb = fmaf(wi1[0], (x0), pb);     \
        pa = fmaf(wi0[1], (x1), pa);  pb = fmaf(wi1[1], (x1), pb);     \
        pa = fmaf(wi0[2], (x2), pa);  pb = fmaf(wi1[2], (x2), pb);     \
        pa = fmaf(wi0[3], (x3), pa);  pb = fmaf(wi1[3], (x3), pb);     \
        pa = fmaf(wi0[4], (x4), pa);  pb = fmaf(wi1[4], (x4), pb);     \
    } while (0)

    // dependent part of one step: z-FMAs + paired ex2/rcp tanh
#define STEP(pa, pb)                                                   \
    do {                                                               \
        float z0 = fmaf(a01, h1, fmaf(a00, h0, pa));                   \
        float z1 = fmaf(a11, h1, fmaf(a10, h0, pb));                   \
        float e0 = ex2_approx(z0);                                     \
        float e1 = ex2_approx(z1);                                     \
        float r0 = rcp_approx(e0 + 1.0f);                              \
        float r1 = rcp_approx(e1 + 1.0f);                              \
        h0 = fmaf(-2.0f, r0, 1.0f);                                    \
        h1 = fmaf(-2.0f, r1, 1.0f);                                    \
    } while (0)

    const float4* myrow0 = &tile[wid * 2 * WTILE + lane * RP];
    auto compute_chunk = [&](int buf) {
        const float4* __restrict__ myrow = myrow0 + buf * WTILE;
#pragma unroll
        for (int j = 0; j < 8; ++j) {               // 8 groups of 4 steps
            float4 q0 = myrow[5 * j + 0];
            float4 q1 = myrow[5 * j + 1];
            float4 q2 = myrow[5 * j + 2];
            float4 q3 = myrow[5 * j + 3];
            float4 q4 = myrow[5 * j + 4];
            // all projections for the group first (off the critical chain)
            float p00 = c0, p01 = c1, p10 = c0, p11 = c1;
            float p20 = c0, p21 = c1, p30 = c0, p31 = c1;
            PROJ(p00, p01, q0.x, q0.y, q0.z, q0.w, q1.x);
            PROJ(p10, p11, q1.y, q1.z, q1.w, q2.x, q2.y);
            PROJ(p20, p21, q2.z, q2.w, q3.x, q3.y, q3.z);
            PROJ(p30, p31, q3.w, q4.x, q4.y, q4.z, q4.w);
            // serial chain
            STEP(p00, p01);
            STEP(p10, p11);
            STEP(p20, p21);
            STEP(p30, p31);
        }
    };

    // ---- per-warp software pipeline: double buffer ----
    issue_chunk(0, 0);
    issue_chunk(1, 1);

    for (int g = 0; g < NCH - 1; ++g) {
        asm volatile("cp.async.wait_group 1;");
        __syncwarp();
        compute_chunk(g & 1);
        if (g + 2 < NCH)
            issue_chunk(g + 2, g & 1);
    }
    asm volatile("cp.async.wait_group 0;");
    __syncwarp();
    compute_chunk((NCH - 1) & 1);
#undef PROJ
#undef STEP

    // ---- head: relu(h) -> FC(2->128) + relu -> FC(128->1) ----
    const float r0 = fmaxf(h0, 0.0f);
    const float r1 = fmaxf(h1, 0.0f);
    const float2* __restrict__ W1v = reinterpret_cast<const float2*>(W1);
    float acc = b2[0];
#pragma unroll 8
    for (int f = 0; f < 128; ++f) {
        float2 w = W1v[f];
        float t = fmaf(w.x, r0, fmaf(w.y, r1, b1[f]));
        acc = fmaf(fmaxf(t, 0.0f), W2[f], acc);
    }
    out[warp_row0 + lane] = acc;
}

extern "C" void kernel_launch(void* const* d_in, const int* in_sizes, int n_in,
                              void* d_out, int out_size)
{
    const float* x   = (const float*)d_in[0];
    const float* Wih = (const float*)d_in[1];
    const float* Whh = (const float*)d_in[2];
    const float* bih = (const float*)d_in[3];
    const float* bhh = (const float*)d_in[4];
    const float* W1  = (const float*)d_in[5];
    const float* b1  = (const float*)d_in[6];
    const float* W2  = (const float*)d_in[7];
    const float* b2  = (const float*)d_in[8];
    float* out = (float*)d_out;

    static int smem_set = 0;
    if (!smem_set) {
        cudaFuncSetAttribute(rnn1_kernel,
                             cudaFuncAttributeMaxDynamicSharedMemorySize,
                             SMEM_BYTES);
        smem_set = 1;
    }

    rnn1_kernel<<<128, 128, SMEM_BYTES>>>(x, Wih, Whh, bih, bhh,
                                          W1, b1, W2, b2, out);
}

// round 7
// speedup vs baseline: 1.4539x; 1.2709x over previous
#include <cuda_runtime.h>
#include <cuda_bf16.h>
#include <cstdint>

// RNN1: B=16384, T=256, I=5, H=2, F=128, C=1
// 128-thread blocks (4 warps -> 4 SMSPs), 32 rows/warp, lane = row.
// cp.async double-buffered staging (proven). Serial-chain optimization:
// tanh.approx.f32 (1 MUFU) for steps 0..223, exact ex2/rcp tanh for the
// last 32 steps (approx error decays through the contraction; exact tail
// restores precision).

#define NCH       8
#define F4C       40
#define RP        41
#define WTILE     (32 * RP)
#define SMEM_BYTES (4 * 2 * WTILE * 16)

__device__ __forceinline__ float ex2_approx(float x) {
    float y; asm("ex2.approx.f32 %0, %1;" : "=f"(y) : "f"(x)); return y;
}
__device__ __forceinline__ float rcp_approx(float x) {
    float y; asm("rcp.approx.f32 %0, %1;" : "=f"(y) : "f"(x)); return y;
}
__device__ __forceinline__ float tanh_fast(float x) {
    float y; asm("tanh.approx.f32 %0, %1;" : "=f"(y) : "f"(x)); return y;
}

__device__ __forceinline__ void cp_async16(unsigned int dst_smem, const void* src) {
    asm volatile("cp.async.cg.shared.global [%0], [%1], 16;\n"
                 :: "r"(dst_smem), "l"(src));
}

extern __shared__ float4 tile[];   // [4 warps][2 bufs][32 rows][41 f4]

__global__ void __launch_bounds__(128, 1) rnn1_kernel(
    const float* __restrict__ x,
    const float* __restrict__ Wih, const float* __restrict__ Whh,
    const float* __restrict__ bih, const float* __restrict__ bhh,
    const float* __restrict__ W1,  const float* __restrict__ b1,
    const float* __restrict__ W2,  const float* __restrict__ b2,
    float* __restrict__ out)
{
    const int lane = threadIdx.x & 31;
    const int wid  = threadIdx.x >> 5;
    const int warp_row0 = blockIdx.x * 128 + wid * 32;

    // UNSCALED weights (tanh.approx takes the raw argument)
    float wi0[5], wi1[5];
#pragma unroll
    for (int i = 0; i < 5; ++i) { wi0[i] = Wih[i]; wi1[i] = Wih[5 + i]; }
    const float a00 = Whh[0], a01 = Whh[1];
    const float a10 = Whh[2], a11 = Whh[3];
    const float c0 = bih[0] + bhh[0];
    const float c1 = bih[1] + bhh[1];
    const float S = 2.885390081777926815f;  // 2/ln(2), applied only in exact tail

    const float4* __restrict__ xw =
        reinterpret_cast<const float4*>(x) + (size_t)warp_row0 * 320;

    const int grp = lane >> 3;
    const int sub = lane & 7;
    const float4* src_base = xw + grp * 320 + sub;

    const unsigned int smem0 = (unsigned int)__cvta_generic_to_shared(tile);
    const unsigned int dst0 =
        smem0 + (unsigned int)((wid * 2 * WTILE) + grp * RP + sub) * 16u;
    const unsigned int dst1 = dst0 + (unsigned int)WTILE * 16u;

    auto issue_chunk = [&](int chunk, int buf) {
        const float4* s = src_base + chunk * F4C;
        const unsigned int d = buf ? dst1 : dst0;
#pragma unroll
        for (int j = 0; j < 8; ++j)
#pragma unroll
            for (int k = 0; k < 5; ++k)
                cp_async16(d + (unsigned int)(j * 4 * RP + k * 8) * 16u,
                           s + j * 4 * 320 + k * 8);
        asm volatile("cp.async.commit_group;");
    };

    float h0 = 0.0f, h1 = 0.0f;

#define PROJ(pa, pb, x0, x1, x2, x3, x4)                               \
    do {                                                               \
        pa = fmaf(wi0[0], (x0), pa);  pb = fmaf(wi1[0], (x0), pb);     \
        pa = fmaf(wi0[1], (x1), pa);  pb = fmaf(wi1[1], (x1), pb);     \
        pa = fmaf(wi0[2], (x2), pa);  pb = fmaf(wi1[2], (x2), pb);     \
        pa = fmaf(wi0[3], (x3), pa);  pb = fmaf(wi1[3], (x3), pb);     \
        pa = fmaf(wi0[4], (x4), pa);  pb = fmaf(wi1[4], (x4), pb);     \
    } while (0)

    // fast step: 2 serial FMAs + ONE MUFU per hidden unit
#define STEP_A(pa, pb)                                                 \
    do {                                                               \
        float z0 = fmaf(a01, h1, fmaf(a00, h0, pa));                   \
        float z1 = fmaf(a11, h1, fmaf(a10, h0, pb));                   \
        h0 = tanh_fast(z0);                                            \
        h1 = tanh_fast(z1);                                            \
    } while (0)

    // exact step: tanh via ex2/rcp (arg scaled by 2/ln2 on the fly)
#define STEP_E(pa, pb)                                                 \
    do {                                                               \
        float z0 = fmaf(a01, h1, fmaf(a00, h0, pa));                   \
        float z1 = fmaf(a11, h1, fmaf(a10, h0, pb));                   \
        float e0 = ex2_approx(S * z0);                                 \
        float e1 = ex2_approx(S * z1);                                 \
        float r0 = rcp_approx(e0 + 1.0f);                              \
        float r1 = rcp_approx(e1 + 1.0f);                              \
        h0 = fmaf(-2.0f, r0, 1.0f);                                    \
        h1 = fmaf(-2.0f, r1, 1.0f);                                    \
    } while (0)

    const float4* myrow0 = &tile[wid * 2 * WTILE + lane * RP];

#define CHUNK_BODY(STEPM, buf)                                         \
    do {                                                               \
        const float4* __restrict__ myrow = myrow0 + (buf) * WTILE;     \
        _Pragma("unroll")                                              \
        for (int j = 0; j < 8; ++j) {                                  \
            float4 q0 = myrow[5 * j + 0];                              \
            float4 q1 = myrow[5 * j + 1];                              \
            float4 q2 = myrow[5 * j + 2];                              \
            float4 q3 = myrow[5 * j + 3];                              \
            float4 q4 = myrow[5 * j + 4];                              \
            float p00 = c0, p01 = c1, p10 = c0, p11 = c1;              \
            float p20 = c0, p21 = c1, p30 = c0, p31 = c1;              \
            PROJ(p00, p01, q0.x, q0.y, q0.z, q0.w, q1.x);              \
            PROJ(p10, p11, q1.y, q1.z, q1.w, q2.x, q2.y);              \
            PROJ(p20, p21, q2.z, q2.w, q3.x, q3.y, q3.z);              \
            PROJ(p30, p31, q3.w, q4.x, q4.y, q4.z, q4.w);              \
            STEPM(p00, p01);                                           \
            STEPM(p10, p11);                                           \
            STEPM(p20, p21);                                           \
            STEPM(p30, p31);                                           \
        }                                                              \
    } while (0)

    // ---- pipeline: chunks 0..6 approx, chunk 7 exact ----
    issue_chunk(0, 0);
    issue_chunk(1, 1);

    for (int g = 0; g < NCH - 1; ++g) {             // g = 0..6 (approx)
        asm volatile("cp.async.wait_group 1;");
        __syncwarp();
        CHUNK_BODY(STEP_A, g & 1);
        if (g + 2 < NCH)
            issue_chunk(g + 2, g & 1);
    }
    asm volatile("cp.async.wait_group 0;");
    __syncwarp();
    CHUNK_BODY(STEP_E, (NCH - 1) & 1);              // last 32 steps exact
#undef PROJ
#undef STEP_A
#undef STEP_E
#undef CHUNK_BODY

    // ---- head: relu(h) -> FC(2->128) + relu -> FC(128->1) ----
    const float r0 = fmaxf(h0, 0.0f);
    const float r1 = fmaxf(h1, 0.0f);
    const float2* __restrict__ W1v = reinterpret_cast<const float2*>(W1);
    float acc = b2[0];
#pragma unroll 8
    for (int f = 0; f < 128; ++f) {
        float2 w = W1v[f];
        float t = fmaf(w.x, r0, fmaf(w.y, r1, b1[f]));
        acc = fmaf(fmaxf(t, 0.0f), W2[f], acc);
    }
    out[warp_row0 + lane] = acc;
}

extern "C" void kernel_launch(void* const* d_in, const int* in_sizes, int n_in,
                              void* d_out, int out_size)
{
    const float* x   = (const float*)d_in[0];
    const float* Wih = (const float*)d_in[1];
    const float* Whh = (const float*)d_in[2];
    const float* bih = (const float*)d_in[3];
    const float* bhh = (const float*)d_in[4];
    const float* W1  = (const float*)d_in[5];
    const float* b1  = (const float*)d_in[6];
    const float* W2  = (const float*)d_in[7];
    const float* b2  = (const float*)d_in[8];
    float* out = (float*)d_out;

    static int smem_set = 0;
    if (!smem_set) {
        cudaFuncSetAttribute(rnn1_kernel,
                             cudaFuncAttributeMaxDynamicSharedMemorySize,
                             SMEM_BYTES);
        smem_set = 1;
    }

    rnn1_kernel<<<128, 128, SMEM_BYTES>>>(x, Wih, Whh, bih, bhh,
                                          W1, b1, W2, b2, out);
}